// round 17
// baseline (speedup 1.0000x reference)
#include <cuda_runtime.h>
#include <cuda_fp16.h>
#include <math.h>
#include <stdint.h>

#define L_LAYERS 250
#define N_TRACES 600
#define N_THETA  30
#define NI   249                 // interfaces (ref row 249 is zero -> dropped)
#define NCOL 18000               // N_TRACES * N_THETA
#define NP   18048               // padded R plane pitch (cols)
#define KPAD 256                 // padded K
#define TOTAL (NI * NCOL)
#define HTOTAL (TOTAL / 2)       // angle-pair count
#define WELEMS (256 * 256)

// fp16 planes. __device__ globals are zero-initialized at module load.
// Pad regions (rows >= 249, cols >= 18000) are NEVER written by any kernel,
// so they remain zero across all graph replays.
// g_Wp: W packed with the k-permutation making HMMA A-fragments 8-byte
// contiguous (round-15 verified): within each 16-k group,
// pos(k) = ((k&6)<<1) | ((k&8)>>2) | (k&1).
__device__ __half g_Rh[KPAD * NP];
__device__ __half g_Wp[256 * 256];

__device__ __forceinline__ float sqrt_approx(float x) {
    float r;
    asm("sqrt.approx.f32 %0, %1;" : "=f"(r) : "f"(x));
    return r;
}

// ---- packed f32x2 helpers (sm_100+ base ISA; round-16 verified) ----
typedef unsigned long long u64t;
__device__ __forceinline__ u64t pk2(float a, float b) {
    u64t r; asm("mov.b64 %0, {%1, %2};" : "=l"(r) : "f"(a), "f"(b)); return r;
}
__device__ __forceinline__ u64t bc2(float a) { return pk2(a, a); }
__device__ __forceinline__ void up2(u64t v, float& a, float& b) {
    asm("mov.b64 {%0, %1}, %2;" : "=f"(a), "=f"(b) : "l"(v));
}
__device__ __forceinline__ u64t mul2(u64t a, u64t b) {
    u64t d; asm("mul.rn.f32x2 %0, %1, %2;" : "=l"(d) : "l"(a), "l"(b)); return d;
}
__device__ __forceinline__ u64t add2(u64t a, u64t b) {
    u64t d; asm("add.rn.f32x2 %0, %1, %2;" : "=l"(d) : "l"(a), "l"(b)); return d;
}
__device__ __forceinline__ u64t fma2(u64t a, u64t b, u64t c) {
    u64t d; asm("fma.rn.f32x2 %0, %1, %2, %3;" : "=l"(d) : "l"(a), "l"(b), "l"(c)); return d;
}
__device__ __forceinline__ u64t neg2(u64t a) { return a ^ 0x8000000080000000ULL; }
__device__ __forceinline__ u64t sqrt2c(u64t a) {
    float x, y; up2(a, x, y);
    x = sqrt_approx(fmaxf(x, 0.f));
    y = sqrt_approx(fmaxf(y, 0.f));
    return pk2(x, y);
}

// ---------------------------------------------------------------------------
// Phase 1 (fused, round-16 verified): exact Zoeppritz Rpp via Aki & Richards
// closed form, f32x2-packed angle pairs. Tail blocks pack W into g_Wp
// (k-permuted fragment-linear layout, round-15 verified).
// ---------------------------------------------------------------------------
__global__ void zoe_phase1(const float* __restrict__ vp,
                           const float* __restrict__ vs,
                           const float* __restrict__ rho,
                           const float* __restrict__ theta,
                           const float* __restrict__ W) {
    int gidx = blockIdx.x * 256 + threadIdx.x;

    if (gidx >= HTOTAL) {
        int idx = gidx - HTOTAL;
        if (idx < WELEMS) {
            int r = idx >> 8, k = idx & 255;
            float v = (r < L_LAYERS && k < L_LAYERS) ? W[r * L_LAYERS + k] : 0.f;
            int p16 = ((k & 6) << 1) | ((k & 8) >> 2) | (k & 1);
            int kpos = (k & 240) | p16;
            g_Wp[r * 256 + kpos] = __float2half(v);
        }
        return;
    }

    __shared__ float s_sth[N_THETA], s_cth[N_THETA];
    int tid = threadIdx.x;
    if (tid < N_THETA) {
        float sv, cv;
        sincosf(theta[tid], &sv, &cv);
        s_sth[tid] = sv;
        s_cth[tid] = cv;
    }
    __syncthreads();

    int l   = gidx / (NCOL / 2);
    int rem = gidx - l * (NCOL / 2);
    int t   = rem / (N_THETA / 2);
    int ap  = rem - t * (N_THETA / 2);
    int a0  = ap * 2;
    int n   = t * N_THETA + a0;

    float a1 = vp[l * N_TRACES + t],  a2 = vp[(l + 1) * N_TRACES + t];
    float b1 = vs[l * N_TRACES + t],  b2 = vs[(l + 1) * N_TRACES + t];
    float r1 = rho[l * N_TRACES + t], r2 = rho[(l + 1) * N_TRACES + t];

    float inva1 = __fdividef(1.f, a1);
    float dsc  = 2.f * r2 * (b2 * b2) - 2.f * r1 * (b1 * b1);

    u64t vInva1 = bc2(inva1);
    u64t vA1 = bc2(a1),   vA2 = bc2(a2);
    u64t vB1 = bc2(b1),   vB2 = bc2(b2);
    u64t vR1 = bc2(r1),   vR2 = bc2(r2);
    u64t vD  = bc2(dsc);
    u64t vDrho = bc2(r2 - r1);
    u64t vA1B2 = bc2(a1 * b2);
    u64t vA2B1 = bc2(a2 * b1);
    u64t vOne = bc2(1.f);

    u64t sth = pk2(s_sth[a0], s_sth[a0 + 1]);
    u64t cth = pk2(s_cth[a0], s_cth[a0 + 1]);

    u64t p  = mul2(sth, vInva1);
    u64t p2 = mul2(p, p);

    u64t st2 = mul2(p, vA2);
    u64t ct2 = sqrt2c(fma2(neg2(st2), st2, vOne));
    u64t sp1 = mul2(p, vB1);
    u64t cp1 = sqrt2c(fma2(neg2(sp1), sp1, vOne));
    u64t sp2 = mul2(p, vB2);
    u64t cp2 = sqrt2c(fma2(neg2(sp2), sp2, vOne));

    u64t dp2 = mul2(vD, p2);
    u64t A = add2(vDrho, neg2(dp2));
    u64t B = add2(vR2, neg2(dp2));
    u64t C = add2(vR1, dp2);

    u64t X = mul2(mul2(B, cth), vA2);
    u64t Y = mul2(mul2(C, ct2), vA1);
    u64t E = add2(X, Y);
    u64t F = fma2(mul2(B, cp1), vB2, mul2(mul2(C, cp2), vB1));
    u64t Z = mul2(mul2(vD, cth), cp2);
    u64t Aa1b2 = mul2(A, vA1B2);
    u64t G = add2(Aa1b2, neg2(Z));
    u64t H = fma2(neg2(mul2(vD, ct2)), cp1, mul2(A, vA2B1));
    u64t Dd = fma2(E, F, mul2(mul2(G, H), p2));
    u64t num = fma2(add2(X, neg2(Y)), F, neg2(mul2(mul2(add2(Aa1b2, Z), H), p2)));

    float n0f, n1f, d0f, d1f;
    up2(num, n0f, n1f);
    up2(Dd, d0f, d1f);
    float rv0 = __fdividef(n0f, d0f);
    float rv1 = __fdividef(n1f, d1f);

    size_t o = ((size_t)l * NP + n) >> 1;
    reinterpret_cast<__half2*>(g_Rh)[o] =
        __halves2half2(__float2half(rv0), __float2half(rv1));
}

// ---------------------------------------------------------------------------
// Phase 2: out[t, l, a] = sum_k W[l, k] * R[k, n], n = t*30 + a
// ZERO-BLOCK-BARRIER fp16 HMMA GEMM.
//   Block 128m x 128n, 8 warps of 64m x 32n (round-8 proven mapping).
//   B: per-warp PRIVATE 4-stage ring in smem (16k x 32n per stage), filled by
//      the warp's own cp.async, guarded by per-warp wait_group + __syncwarp.
//   A: fragments straight from L2-hot k-permuted g_Wp via LDG.64
//      (round-15 verified path; no A smem, no ldsm for A).
//   NO __syncthreads anywhere.
// Grid 141 x 2 = 282 blocks, 2 blocks/SM, 16 decoupled warps/SM.
// ---------------------------------------------------------------------------
#define BWPITCH 40                   // 32 + 8 pad halves (80B rows)
#define BWSTG (16 * BWPITCH)         // 640 halves per stage

__device__ __forceinline__ uint32_t smaddr(const void* p) {
    return (uint32_t)__cvta_generic_to_shared(p);
}
__device__ __forceinline__ void ldsm4t(uint32_t a[4], uint32_t addr) {
    asm volatile("ldmatrix.sync.aligned.m8n8.x4.trans.shared.b16 {%0,%1,%2,%3}, [%4];"
                 : "=r"(a[0]), "=r"(a[1]), "=r"(a[2]), "=r"(a[3]) : "r"(addr));
}
__device__ __forceinline__ void mma16816(float c[4], const uint32_t a[4], const uint32_t b[2]) {
    asm volatile("mma.sync.aligned.m16n8k16.row.col.f32.f16.f16.f32 "
                 "{%0,%1,%2,%3}, {%4,%5,%6,%7}, {%8,%9}, {%0,%1,%2,%3};"
                 : "+f"(c[0]), "+f"(c[1]), "+f"(c[2]), "+f"(c[3])
                 : "r"(a[0]), "r"(a[1]), "r"(a[2]), "r"(a[3]), "r"(b[0]), "r"(b[1]));
}
#define CP16(dst, src) \
    asm volatile("cp.async.ca.shared.global [%0], [%1], 16;" :: "r"(dst), "l"(src))
#define CP_COMMIT() asm volatile("cp.async.commit_group;")
#define CP_WAIT(n)  asm volatile("cp.async.wait_group %0;" :: "n"(n))

__global__ __launch_bounds__(256, 2)
void zoe_gemm(float* __restrict__ out) {
    // per-warp private B rings: [warp][stage][k-row][n-col]
    __shared__ __half Bw[8][4][16][BWPITCH];   // 40960 B

    int tid = threadIdx.x;
    int wid = tid >> 5, lane = tid & 31;
    int bm = blockIdx.y * 128;
    int bn = blockIdx.x * 128;

    int wm = (wid >> 2) * 64;                  // 0 or 64
    int wn = (wid & 3) * 32;                   // 0,32,64,96

    // B fill mapping (per warp): 64 CP16 per stage, 2 per lane.
    // c = lane + 32*i : row = c>>2 (0..15), chunk = c&3 (16B units)
    int f_row0 = lane >> 2;                    // rows for i=0: 0..7
    int f_chk0 = (lane & 3) * 8;               // halves offset
    const __half* pB = &g_Rh[bn + wn];         // + (k0+row)*NP + chunk

    // B fragment mapping (proven): ldsm4t x2 per step
    int r8 = lane >> 3, i8 = lane & 7;
    int b_fkrow = (r8 & 1) * 8 + i8;
    int b_fncol = (r8 >> 1) * 8;

    // A fragment pointers (k-permuted g_Wp; round-15 verified)
    int g = lane >> 2, tg = lane & 3;
    const __half* pA0 = &g_Wp[(bm + wm + g) * 256 + tg * 4];
    const __half* pA1 = pA0 + 8 * 256;

    float acc[4][4][4];
#pragma unroll
    for (int mt = 0; mt < 4; mt++)
#pragma unroll
        for (int nt = 0; nt < 4; nt++)
#pragma unroll
            for (int e = 0; e < 4; e++) acc[mt][nt][e] = 0.f;

    // ---- per-warp prologue: stages 0..2 ----
#pragma unroll
    for (int s = 0; s < 3; s++) {
        int k0 = s * 16;
#pragma unroll
        for (int i = 0; i < 2; i++) {
            int row = f_row0 + i * 8;
            uint32_t dst = smaddr(&Bw[wid][s][row][f_chk0]);
            CP16(dst, pB + (size_t)(k0 + row) * NP + f_chk0);
        }
        CP_COMMIT();
    }

    // ---- 16 k-steps, per-warp pipeline, NO block barriers ----
#pragma unroll
    for (int ks = 0; ks < 16; ks++) {
        if (ks <= 13) { CP_WAIT(2); }
        else if (ks == 14) { CP_WAIT(1); }
        else { CP_WAIT(0); }
        __syncwarp();

        // refill stage ks+3 into buffer (ks+3)&3
        if (ks + 3 < 16) {
            int k0 = (ks + 3) * 16;
            int nb = (ks + 3) & 3;
#pragma unroll
            for (int i = 0; i < 2; i++) {
                int row = f_row0 + i * 8;
                uint32_t dst = smaddr(&Bw[wid][nb][row][f_chk0]);
                CP16(dst, pB + (size_t)(k0 + row) * NP + f_chk0);
            }
            CP_COMMIT();
        }

        int buf = ks & 3;
        uint32_t bBase = smaddr(&Bw[wid][buf][b_fkrow][b_fncol]);

        uint32_t bhf[4][2];
#pragma unroll
        for (int pair = 0; pair < 2; pair++) {
            uint32_t t4[4];
            ldsm4t(t4, bBase + pair * 32);
            bhf[pair * 2][0] = t4[0]; bhf[pair * 2][1] = t4[1];
            bhf[pair * 2 + 1][0] = t4[2]; bhf[pair * 2 + 1][1] = t4[3];
        }

#pragma unroll
        for (int mt = 0; mt < 4; mt++) {
            uint2 a02 = *(const uint2*)(pA0 + mt * 16 * 256 + ks * 16);
            uint2 a13 = *(const uint2*)(pA1 + mt * 16 * 256 + ks * 16);
            uint32_t ahf[4] = {a02.x, a13.x, a02.y, a13.y};
#pragma unroll
            for (int nt = 0; nt < 4; nt++) {
                mma16816(acc[mt][nt], ahf, bhf[nt]);
            }
        }
    }

    // ---- epilogue (proven) ----
#pragma unroll
    for (int mt = 0; mt < 4; mt++) {
#pragma unroll
        for (int nt = 0; nt < 4; nt++) {
            int l0 = bm + wm + mt * 16 + (lane >> 2);
            int n0 = bn + wn + nt * 8 + (lane & 3) * 2;
#pragma unroll
            for (int e = 0; e < 4; e++) {
                int l = l0 + (e >> 1) * 8;
                int n = n0 + (e & 1);
                if (l < L_LAYERS && n < NCOL) {
                    int t = n / N_THETA;
                    int a = n - t * N_THETA;
                    out[t * (L_LAYERS * N_THETA) + l * N_THETA + a] = acc[mt][nt][e];
                }
            }
        }
    }
}

extern "C" void kernel_launch(void* const* d_in, const int* in_sizes, int n_in,
                              void* d_out, int out_size) {
    const float* vp      = (const float*)d_in[0];
    const float* vs      = (const float*)d_in[1];
    const float* rho     = (const float*)d_in[2];
    const float* theta   = (const float*)d_in[3];
    const float* wavemat = (const float*)d_in[4];
    float* out = (float*)d_out;

    int nblk = (HTOTAL + WELEMS + 255) / 256;
    zoe_phase1<<<nblk, 256>>>(vp, vs, rho, theta, wavemat);

    dim3 grid((NCOL + 127) / 128, 2);
    zoe_gemm<<<grid, 256>>>(out);
}